// round 2
// baseline (speedup 1.0000x reference)
#include <cuda_runtime.h>
#include <cstdint>

#define NHEADS 12
#define HS     64
#define HID    768
#define OUTD   1536
#define NB     8
#define NL     512

// Scratch for rotated q/k in [b, h, l, d] layout (fp32).
__device__ float g_q[NB * NHEADS * NL * HS];
__device__ float g_k[NB * NHEADS * NL * HS];

__device__ __forceinline__ unsigned f2tf32(float x) {
    unsigned r;
    asm("cvt.rna.tf32.f32 %0, %1;" : "=r"(r) : "f"(x));
    return r;
}

__device__ __forceinline__ void mma8(float c[4], const unsigned a[4], const unsigned b[2]) {
    asm volatile(
        "mma.sync.aligned.m16n8k8.row.col.f32.tf32.tf32.f32 "
        "{%0,%1,%2,%3}, {%4,%5,%6,%7}, {%8,%9}, {%0,%1,%2,%3};\n"
        : "+f"(c[0]), "+f"(c[1]), "+f"(c[2]), "+f"(c[3])
        : "r"(a[0]), "r"(a[1]), "r"(a[2]), "r"(a[3]), "r"(b[0]), "r"(b[1]));
}

// ---------------------------------------------------------------------------
// Kernel 1: x = X @ W + b, fused interleaved RoPE, scatter to g_q / g_k.
// X: [4096, 768], W: [768, 1536]. Block tile 128x128, K-step 16.
// 8 warps: warp grid 2(M) x 4(N), warp tile 64x32 -> 4x4 m16n8 mma tiles.
// ---------------------------------------------------------------------------
__global__ __launch_bounds__(256) void k_gemm1_rope(
    const float* __restrict__ X,
    const float* __restrict__ W,
    const float* __restrict__ bias)
{
    __shared__ unsigned As[128][20];   // stride 20: (20m+k)%32 bijective over frag pattern
    __shared__ unsigned Bs[16][136];   // stride 136: (8k+n)%32 bijective

    const int tid  = threadIdx.x;
    const int lane = tid & 31;
    const int warp = tid >> 5;
    const int wm   = warp >> 2;   // 0..1
    const int wn   = warp & 3;    // 0..3
    const int bm   = blockIdx.y;  // 0..31
    const int bn   = blockIdx.x;  // 0..11

    float acc[4][4][4];
    #pragma unroll
    for (int mi = 0; mi < 4; mi++)
        #pragma unroll
        for (int ni = 0; ni < 4; ni++)
            #pragma unroll
            for (int r = 0; r < 4; r++) acc[mi][ni][r] = 0.0f;

    for (int kt = 0; kt < HID; kt += 16) {
        // Load A tile 128x16 (2 float4 per thread), convert to tf32.
        #pragma unroll
        for (int it = 0; it < 2; it++) {
            int j  = it * 256 + tid;       // 0..511 float4 ids
            int r  = j >> 2;
            int c4 = j & 3;
            const float4 v = *(const float4*)&X[(size_t)(bm * 128 + r) * HID + kt + c4 * 4];
            uint4 u = make_uint4(f2tf32(v.x), f2tf32(v.y), f2tf32(v.z), f2tf32(v.w));
            *(uint4*)&As[r][c4 * 4] = u;   // 80B row stride: 16B aligned
        }
        // Load B tile 16x128.
        #pragma unroll
        for (int it = 0; it < 2; it++) {
            int j  = it * 256 + tid;
            int r  = j >> 5;
            int c4 = j & 31;
            const float4 v = *(const float4*)&W[(size_t)(kt + r) * OUTD + bn * 128 + c4 * 4];
            uint4 u = make_uint4(f2tf32(v.x), f2tf32(v.y), f2tf32(v.z), f2tf32(v.w));
            *(uint4*)&Bs[r][c4 * 4] = u;   // 544B row stride: 16B aligned
        }
        __syncthreads();

        #pragma unroll
        for (int kk = 0; kk < 16; kk += 8) {
            unsigned bfr[4][2];
            #pragma unroll
            for (int ni = 0; ni < 4; ni++) {
                int col = wn * 32 + ni * 8 + (lane >> 2);
                bfr[ni][0] = Bs[kk + (lane & 3)][col];
                bfr[ni][1] = Bs[kk + 4 + (lane & 3)][col];
            }
            #pragma unroll
            for (int mi = 0; mi < 4; mi++) {
                unsigned afr[4];
                int row = wm * 64 + mi * 16 + (lane >> 2);
                int kc  = kk + (lane & 3);
                afr[0] = As[row][kc];
                afr[1] = As[row + 8][kc];
                afr[2] = As[row][kc + 4];
                afr[3] = As[row + 8][kc + 4];
                #pragma unroll
                for (int ni = 0; ni < 4; ni++) mma8(acc[mi][ni], afr, bfr[ni]);
            }
        }
        __syncthreads();
    }

    // Epilogue: bias + RoPE + scatter.
    // col layout: head = c>>7, qk = (c>>6)&1, d = c&63, pair = d>>1.
    #pragma unroll
    for (int ni = 0; ni < 4; ni++) {
        int gc = bn * 128 + wn * 32 + ni * 8 + 2 * (lane & 3);  // even
        int h  = gc >> 7;
        int s  = (gc >> 6) & 1;
        int d  = gc & 63;
        int pi = d >> 1;
        // inv_freq = 10000^(-pi/32) = 2^(-pi * log2(10000)/32)
        float inv = exp2f(-(float)pi * (13.287712379549449f / 32.0f));
        float b0 = bias[gc], b1 = bias[gc + 1];
        float* dst = s ? g_k : g_q;
        #pragma unroll
        for (int mi = 0; mi < 4; mi++) {
            int gm0 = bm * 128 + wm * 64 + mi * 16 + (lane >> 2);
            #pragma unroll
            for (int half = 0; half < 2; half++) {
                int r  = gm0 + half * 8;
                int l  = r & (NL - 1);
                int bi = r >> 9;
                float sn, cs;
                sincosf((float)l * inv, &sn, &cs);
                float x1 = acc[mi][ni][half * 2 + 0] + b0;
                float x2 = acc[mi][ni][half * 2 + 1] + b1;
                float o1 = x1 * cs - x2 * sn;
                float o2 = x1 * sn + x2 * cs;
                *(float2*)&dst[(((size_t)bi * NHEADS + h) * NL + l) * HS + d] =
                    make_float2(o1, o2);
            }
        }
    }
}

// ---------------------------------------------------------------------------
// Kernel 2: logits[b,h,m,n] = (q[m,:] . k[n,:]) / 8, masked.
// Per block: one 128x128 tile of one (b,h). K=64 in two 32-wide smem chunks.
// ---------------------------------------------------------------------------
__global__ __launch_bounds__(256) void k_attn(
    const int* __restrict__ am, float* __restrict__ out)
{
    __shared__ unsigned Qs[128][36];   // stride 36: (4m+k)%32 bijective
    __shared__ unsigned Ks[128][36];

    const int tid  = threadIdx.x;
    const int lane = tid & 31;
    const int warp = tid >> 5;
    const int wm   = warp >> 2;
    const int wn   = warp & 3;
    const int z    = blockIdx.z;          // b*12 + h
    const int bi   = z / NHEADS;
    const int m0   = blockIdx.y * 128;
    const int n0   = blockIdx.x * 128;

    float acc[4][4][4];
    #pragma unroll
    for (int mi = 0; mi < 4; mi++)
        #pragma unroll
        for (int ni = 0; ni < 4; ni++)
            #pragma unroll
            for (int r = 0; r < 4; r++) acc[mi][ni][r] = 0.0f;

    for (int ct = 0; ct < 2; ct++) {
        // Load 128x32 chunks of q and k tiles.
        #pragma unroll
        for (int it = 0; it < 4; it++) {
            int j  = it * 256 + tid;   // 0..1023 float4 ids
            int r  = j >> 3;
            int c4 = j & 7;
            const float4 v = *(const float4*)&g_q[((size_t)z * NL + m0 + r) * HS + ct * 32 + c4 * 4];
            *(uint4*)&Qs[r][c4 * 4] =
                make_uint4(f2tf32(v.x), f2tf32(v.y), f2tf32(v.z), f2tf32(v.w));
            const float4 w = *(const float4*)&g_k[((size_t)z * NL + n0 + r) * HS + ct * 32 + c4 * 4];
            *(uint4*)&Ks[r][c4 * 4] =
                make_uint4(f2tf32(w.x), f2tf32(w.y), f2tf32(w.z), f2tf32(w.w));
        }
        __syncthreads();

        #pragma unroll
        for (int kk = 0; kk < 32; kk += 8) {
            unsigned bfr[4][2];
            #pragma unroll
            for (int ni = 0; ni < 4; ni++) {
                int nrow = wn * 32 + ni * 8 + (lane >> 2);
                bfr[ni][0] = Ks[nrow][kk + (lane & 3)];
                bfr[ni][1] = Ks[nrow][kk + 4 + (lane & 3)];
            }
            #pragma unroll
            for (int mi = 0; mi < 4; mi++) {
                unsigned afr[4];
                int row = wm * 64 + mi * 16 + (lane >> 2);
                int kc  = kk + (lane & 3);
                afr[0] = Qs[row][kc];
                afr[1] = Qs[row + 8][kc];
                afr[2] = Qs[row][kc + 4];
                afr[3] = Qs[row + 8][kc + 4];
                #pragma unroll
                for (int ni = 0; ni < 4; ni++) mma8(acc[mi][ni], afr, bfr[ni]);
            }
        }
        __syncthreads();
    }

    // Masks: keep iff am[m] && am[n] && m <= n, else -FLT_MAX (= finfo(f32).min).
    const float NEG = -3.4028234663852886e38f;
    bool mok[4][2];
    #pragma unroll
    for (int mi = 0; mi < 4; mi++)
        #pragma unroll
        for (int half = 0; half < 2; half++)
            mok[mi][half] = am[bi * NL + m0 + wm * 64 + mi * 16 + (lane >> 2) + half * 8] != 0;
    bool nok[4][2];
    #pragma unroll
    for (int ni = 0; ni < 4; ni++) {
        int n = n0 + wn * 32 + ni * 8 + 2 * (lane & 3);
        nok[ni][0] = am[bi * NL + n] != 0;
        nok[ni][1] = am[bi * NL + n + 1] != 0;
    }

    #pragma unroll
    for (int mi = 0; mi < 4; mi++) {
        #pragma unroll
        for (int half = 0; half < 2; half++) {
            int gm = m0 + wm * 64 + mi * 16 + (lane >> 2) + half * 8;
            bool mo = mok[mi][half];
            #pragma unroll
            for (int ni = 0; ni < 4; ni++) {
                int gn = n0 + wn * 32 + ni * 8 + 2 * (lane & 3);
                float v0 = acc[mi][ni][half * 2 + 0] * 0.125f;
                float v1 = acc[mi][ni][half * 2 + 1] * 0.125f;
                float r0 = (mo && nok[ni][0] && gm <= gn)     ? v0 : NEG;
                float r1 = (mo && nok[ni][1] && gm <= gn + 1) ? v1 : NEG;
                *(float2*)&out[((size_t)z * NL + gm) * NL + gn] = make_float2(r0, r1);
            }
        }
    }
}

extern "C" void kernel_launch(void* const* d_in, const int* in_sizes, int n_in,
                              void* d_out, int out_size)
{
    const float* X    = (const float*)d_in[0];   // [8, 512, 768]
    const float* W    = (const float*)d_in[1];   // [768, 1536]
    const float* bias = (const float*)d_in[2];   // [1536]
    const int*   am   = (const int*)d_in[3];     // [8, 512]
    float* out        = (float*)d_out;           // [8, 12, 512, 512]

    (void)in_sizes; (void)n_in; (void)out_size;

    k_gemm1_rope<<<dim3(OUTD / 128, (NB * NL) / 128), 256>>>(X, W, bias);
    k_attn<<<dim3(NL / 128, NL / 128, NB * NHEADS), 256>>>(am, out);
}

// round 3
// speedup vs baseline: 1.3455x; 1.3455x over previous
#include <cuda_runtime.h>
#include <cstdint>

#define NHEADS 12
#define HS     64
#define HID    768
#define OUTD   1536
#define NB     8
#define NL     512

// Scratch for rotated q/k in [b, h, l, d] layout (fp32).
__device__ float g_q[NB * NHEADS * NL * HS];
__device__ float g_k[NB * NHEADS * NL * HS];
// RoPE table: g_sc[l*32 + pairIdx] = (sin, cos)
__device__ float2 g_sc[NL * 32];

__device__ __forceinline__ unsigned f2tf32(float x) {
    unsigned r;
    asm("cvt.rna.tf32.f32 %0, %1;" : "=r"(r) : "f"(x));
    return r;
}

__device__ __forceinline__ void mma8(float c[4], const unsigned a[4], const unsigned b[2]) {
    asm volatile(
        "mma.sync.aligned.m16n8k8.row.col.f32.tf32.tf32.f32 "
        "{%0,%1,%2,%3}, {%4,%5,%6,%7}, {%8,%9}, {%0,%1,%2,%3};\n"
        : "+f"(c[0]), "+f"(c[1]), "+f"(c[2]), "+f"(c[3])
        : "r"(a[0]), "r"(a[1]), "r"(a[2]), "r"(a[3]), "r"(b[0]), "r"(b[1]));
}

__device__ __forceinline__ void cpasync16(void* s, const void* g) {
    unsigned sa = (unsigned)__cvta_generic_to_shared(s);
    asm volatile("cp.async.ca.shared.global [%0], [%1], 16;" :: "r"(sa), "l"(g));
}

// ---------------------------------------------------------------------------
// Kernel 0: RoPE sin/cos table (runs once per launch, ~16K sincosf total).
// ---------------------------------------------------------------------------
__global__ void k_tab() {
    int i  = blockIdx.x * 256 + threadIdx.x;   // 0..16383
    int l  = i >> 5;
    int pi = i & 31;
    float inv = exp2f(-(float)pi * (13.287712379549449f / 32.0f));
    float s, c;
    sincosf((float)l * inv, &s, &c);
    g_sc[i] = make_float2(s, c);
}

// ---------------------------------------------------------------------------
// Kernel 1: x = X @ W + b, fused interleaved RoPE, scatter to g_q / g_k.
// Block tile 128x128, K-step 16, 4-stage cp.async pipeline.
// 8 warps: 2(M) x 4(N), warp tile 64x32.
// smem (dynamic): A stages 128x20 fp32, B stages 16x136 fp32.
// ---------------------------------------------------------------------------
#define G1_ASTRIDE 20
#define G1_BSTRIDE 136
#define G1_ASTAGE  (128 * G1_ASTRIDE)
#define G1_BSTAGE  (16 * G1_BSTRIDE)
#define G1_SMEM    (4 * (G1_ASTAGE + G1_BSTAGE) * 4)

__global__ __launch_bounds__(256) void k_gemm1_rope(
    const float* __restrict__ X,
    const float* __restrict__ W,
    const float* __restrict__ bias)
{
    extern __shared__ float sh[];
    float* AsBase = sh;
    float* BsBase = sh + 4 * G1_ASTAGE;

    const int tid  = threadIdx.x;
    const int lane = tid & 31;
    const int warp = tid >> 5;
    const int wm   = warp >> 2;
    const int wn   = warp & 3;
    const int bm   = blockIdx.y;
    const int bn   = blockIdx.x;

    float acc[4][4][4];
    #pragma unroll
    for (int mi = 0; mi < 4; mi++)
        #pragma unroll
        for (int ni = 0; ni < 4; ni++)
            #pragma unroll
            for (int r = 0; r < 4; r++) acc[mi][ni][r] = 0.0f;

    const int ar  = tid >> 2;            // A row handled by this thread (pairs)
    const int ac4 = tid & 3;
    const int br  = tid >> 5;
    const int bc4 = tid & 31;

    auto loadStage = [&](int kt, int s) {
        float* A = AsBase + s * G1_ASTAGE;
        float* B = BsBase + s * G1_BSTAGE;
        #pragma unroll
        for (int it = 0; it < 2; it++) {
            int r  = ar + it * 64;
            cpasync16(&A[r * G1_ASTRIDE + ac4 * 4],
                      &X[(size_t)(bm * 128 + r) * HID + kt + ac4 * 4]);
        }
        #pragma unroll
        for (int it = 0; it < 2; it++) {
            int r = br + it * 8;
            cpasync16(&B[r * G1_BSTRIDE + bc4 * 4],
                      &W[(size_t)(kt + r) * OUTD + bn * 128 + bc4 * 4]);
        }
    };

    const int NK = HID / 16;   // 48
    #pragma unroll
    for (int s = 0; s < 3; s++) {
        loadStage(s * 16, s);
        asm volatile("cp.async.commit_group;");
    }

    for (int i = 0; i < NK; i++) {
        asm volatile("cp.async.wait_group 2;");
        __syncthreads();
        if (i + 3 < NK) loadStage((i + 3) * 16, (i + 3) & 3);
        asm volatile("cp.async.commit_group;");

        const float* A = AsBase + (i & 3) * G1_ASTAGE;
        const float* B = BsBase + (i & 3) * G1_BSTAGE;

        #pragma unroll
        for (int kk = 0; kk < 16; kk += 8) {
            unsigned bfr[4][2];
            #pragma unroll
            for (int ni = 0; ni < 4; ni++) {
                int col = wn * 32 + ni * 8 + (lane >> 2);
                bfr[ni][0] = f2tf32(B[(kk + (lane & 3)) * G1_BSTRIDE + col]);
                bfr[ni][1] = f2tf32(B[(kk + 4 + (lane & 3)) * G1_BSTRIDE + col]);
            }
            #pragma unroll
            for (int mi = 0; mi < 4; mi++) {
                unsigned afr[4];
                int row = wm * 64 + mi * 16 + (lane >> 2);
                int kc  = kk + (lane & 3);
                afr[0] = f2tf32(A[row * G1_ASTRIDE + kc]);
                afr[1] = f2tf32(A[(row + 8) * G1_ASTRIDE + kc]);
                afr[2] = f2tf32(A[row * G1_ASTRIDE + kc + 4]);
                afr[3] = f2tf32(A[(row + 8) * G1_ASTRIDE + kc + 4]);
                #pragma unroll
                for (int ni = 0; ni < 4; ni++) mma8(acc[mi][ni], afr, bfr[ni]);
            }
        }
    }

    // Epilogue: bias + RoPE (table) + scatter.
    #pragma unroll
    for (int ni = 0; ni < 4; ni++) {
        int gc = bn * 128 + wn * 32 + ni * 8 + 2 * (lane & 3);  // even col
        int h  = gc >> 7;
        int s  = (gc >> 6) & 1;
        int d  = gc & 63;
        int pi = d >> 1;
        float b0 = bias[gc], b1 = bias[gc + 1];
        float* dst = s ? g_k : g_q;
        #pragma unroll
        for (int mi = 0; mi < 4; mi++) {
            int gm0 = bm * 128 + wm * 64 + mi * 16 + (lane >> 2);
            #pragma unroll
            for (int half = 0; half < 2; half++) {
                int r  = gm0 + half * 8;
                int l  = r & (NL - 1);
                int bi = r >> 9;
                float2 sc = g_sc[l * 32 + pi];
                float x1 = acc[mi][ni][half * 2 + 0] + b0;
                float x2 = acc[mi][ni][half * 2 + 1] + b1;
                float o1 = x1 * sc.y - x2 * sc.x;
                float o2 = x1 * sc.x + x2 * sc.y;
                *(float2*)&dst[(((size_t)bi * NHEADS + h) * NL + l) * HS + d] =
                    make_float2(o1, o2);
            }
        }
    }
}

// ---------------------------------------------------------------------------
// Kernel 2: logits[b,h,m,n] = (q[m,:] . k[n,:]) / 8, masked.
// Full-K (64) smem tiles, single sync. Fully-below-diagonal tiles fast-fill NEG.
// smem (dynamic): Qs/Ks 128x68 fp32 each.
// ---------------------------------------------------------------------------
#define A2_STRIDE 68
#define A2_TILE   (128 * A2_STRIDE)
#define A2_SMEM   (2 * A2_TILE * 4)

__global__ __launch_bounds__(256) void k_attn(
    const int* __restrict__ am, float* __restrict__ out)
{
    extern __shared__ float sh2[];
    float* Qs = sh2;
    float* Ks = sh2 + A2_TILE;

    const int tid  = threadIdx.x;
    const int z    = blockIdx.z;          // b*12 + h
    const int m0   = blockIdx.y * 128;
    const int n0   = blockIdx.x * 128;

    const float NEG = -3.4028234663852886e38f;

    // Fast path: tile entirely strictly-below-diagonal -> all NEG.
    if (m0 >= n0 + 128) {
        const float4 negv = make_float4(NEG, NEG, NEG, NEG);
        #pragma unroll
        for (int it = 0; it < 16; it++) {
            int j = it * 256 + tid;       // 0..4095 float4 ids
            int r = j >> 5;
            int c = j & 31;
            *(float4*)&out[((size_t)z * NL + m0 + r) * NL + n0 + c * 4] = negv;
        }
        return;
    }

    const int lane = tid & 31;
    const int warp = tid >> 5;
    const int wm   = warp >> 2;
    const int wn   = warp & 3;
    const int bi   = z / NHEADS;

    // Load full 128x64 q and k tiles via cp.async.
    {
        const int r0 = tid >> 1;          // rows 0..127 (2 threads per row)
        const int c0 = (tid & 1) * 8;     // col group (each thread: 2 float4 = 32 floats? no: 8 floats x ... )
        // 128 rows x 64 floats = 2048 float4; 256 threads -> 8 float4 each.
        #pragma unroll
        for (int it = 0; it < 4; it++) {
            int r = r0 + it * 0; (void)r;
        }
        #pragma unroll
        for (int it = 0; it < 8; it++) {
            int j  = it * 256 + tid;      // float4 id
            int r  = j >> 4;              // 16 float4 per row
            int c4 = j & 15;
            cpasync16(&Qs[r * A2_STRIDE + c4 * 4],
                      &g_q[((size_t)z * NL + m0 + r) * HS + c4 * 4]);
            cpasync16(&Ks[r * A2_STRIDE + c4 * 4],
                      &g_k[((size_t)z * NL + n0 + r) * HS + c4 * 4]);
        }
        (void)c0;
    }
    asm volatile("cp.async.commit_group;");

    float acc[4][4][4];
    #pragma unroll
    for (int mi = 0; mi < 4; mi++)
        #pragma unroll
        for (int ni = 0; ni < 4; ni++)
            #pragma unroll
            for (int r = 0; r < 4; r++) acc[mi][ni][r] = 0.0f;

    asm volatile("cp.async.wait_group 0;");
    __syncthreads();

    #pragma unroll
    for (int kk = 0; kk < 64; kk += 8) {
        unsigned bfr[4][2];
        #pragma unroll
        for (int ni = 0; ni < 4; ni++) {
            int nrow = wn * 32 + ni * 8 + (lane >> 2);
            bfr[ni][0] = f2tf32(Ks[nrow * A2_STRIDE + kk + (lane & 3)]);
            bfr[ni][1] = f2tf32(Ks[nrow * A2_STRIDE + kk + 4 + (lane & 3)]);
        }
        #pragma unroll
        for (int mi = 0; mi < 4; mi++) {
            unsigned afr[4];
            int row = wm * 64 + mi * 16 + (lane >> 2);
            int kc  = kk + (lane & 3);
            afr[0] = f2tf32(Qs[row * A2_STRIDE + kc]);
            afr[1] = f2tf32(Qs[(row + 8) * A2_STRIDE + kc]);
            afr[2] = f2tf32(Qs[row * A2_STRIDE + kc + 4]);
            afr[3] = f2tf32(Qs[(row + 8) * A2_STRIDE + kc + 4]);
            #pragma unroll
            for (int ni = 0; ni < 4; ni++) mma8(acc[mi][ni], afr, bfr[ni]);
        }
    }

    // Masks: keep iff am[m] && am[n] && m <= n, else NEG.
    bool mok[4][2];
    #pragma unroll
    for (int mi = 0; mi < 4; mi++)
        #pragma unroll
        for (int half = 0; half < 2; half++)
            mok[mi][half] = am[bi * NL + m0 + wm * 64 + mi * 16 + (lane >> 2) + half * 8] != 0;
    bool nok[4][2];
    #pragma unroll
    for (int ni = 0; ni < 4; ni++) {
        int n = n0 + wn * 32 + ni * 8 + 2 * (lane & 3);
        nok[ni][0] = am[bi * NL + n] != 0;
        nok[ni][1] = am[bi * NL + n + 1] != 0;
    }

    #pragma unroll
    for (int mi = 0; mi < 4; mi++) {
        #pragma unroll
        for (int half = 0; half < 2; half++) {
            int gm = m0 + wm * 64 + mi * 16 + (lane >> 2) + half * 8;
            bool mo = mok[mi][half];
            #pragma unroll
            for (int ni = 0; ni < 4; ni++) {
                int gn = n0 + wn * 32 + ni * 8 + 2 * (lane & 3);
                float v0 = acc[mi][ni][half * 2 + 0] * 0.125f;
                float v1 = acc[mi][ni][half * 2 + 1] * 0.125f;
                float r0 = (mo && nok[ni][0] && gm <= gn)     ? v0 : NEG;
                float r1 = (mo && nok[ni][1] && gm <= gn + 1) ? v1 : NEG;
                *(float2*)&out[((size_t)z * NL + gm) * NL + gn] = make_float2(r0, r1);
            }
        }
    }
}

extern "C" void kernel_launch(void* const* d_in, const int* in_sizes, int n_in,
                              void* d_out, int out_size)
{
    const float* X    = (const float*)d_in[0];   // [8, 512, 768]
    const float* W    = (const float*)d_in[1];   // [768, 1536]
    const float* bias = (const float*)d_in[2];   // [1536]
    const int*   am   = (const int*)d_in[3];     // [8, 512]
    float* out        = (float*)d_out;           // [8, 12, 512, 512]

    (void)in_sizes; (void)n_in; (void)out_size;

    cudaFuncSetAttribute(k_gemm1_rope, cudaFuncAttributeMaxDynamicSharedMemorySize, G1_SMEM);
    cudaFuncSetAttribute(k_attn,       cudaFuncAttributeMaxDynamicSharedMemorySize, A2_SMEM);

    k_tab<<<64, 256>>>();
    k_gemm1_rope<<<dim3(OUTD / 128, (NB * NL) / 128), 256, G1_SMEM>>>(X, W, bias);
    k_attn<<<dim3(NL / 128, NL / 128, NB * NHEADS), 256, A2_SMEM>>>(am, out);
}

// round 4
// speedup vs baseline: 1.4120x; 1.0494x over previous
#include <cuda_runtime.h>
#include <cuda_bf16.h>
#include <cstdint>

#define NHEADS 12
#define HS     64
#define HID    768
#define OUTD   1536
#define NB     8
#define NL     512

// Rotated q/k scratch, packed bf16 pairs: [b, h, l, d/2] (pair = dims d, d+1).
__device__ unsigned g_qh[NB * NHEADS * NL * (HS / 2)];
__device__ unsigned g_kh[NB * NHEADS * NL * (HS / 2)];
// RoPE table: g_sc[l*32 + pairIdx] = (sin, cos)
__device__ float2 g_sc[NL * 32];

__device__ __forceinline__ unsigned packbf(float lo, float hi) {
    __nv_bfloat162 v = __floats2bfloat162_rn(lo, hi);
    return *reinterpret_cast<unsigned*>(&v);
}

__device__ __forceinline__ void mma16(float c[4], const unsigned a[4], const unsigned b[2]) {
    asm volatile(
        "mma.sync.aligned.m16n8k16.row.col.f32.bf16.bf16.f32 "
        "{%0,%1,%2,%3}, {%4,%5,%6,%7}, {%8,%9}, {%0,%1,%2,%3};\n"
        : "+f"(c[0]), "+f"(c[1]), "+f"(c[2]), "+f"(c[3])
        : "r"(a[0]), "r"(a[1]), "r"(a[2]), "r"(a[3]), "r"(b[0]), "r"(b[1]));
}

__device__ __forceinline__ void cpasync16(void* s, const void* g) {
    unsigned sa = (unsigned)__cvta_generic_to_shared(s);
    asm volatile("cp.async.ca.shared.global [%0], [%1], 16;" :: "r"(sa), "l"(g));
}

// ---------------------------------------------------------------------------
// Kernel 0: RoPE sin/cos table.
// ---------------------------------------------------------------------------
__global__ void k_tab() {
    int i  = blockIdx.x * 256 + threadIdx.x;   // 0..16383
    int l  = i >> 5;
    int pi = i & 31;
    float inv = exp2f(-(float)pi * (13.287712379549449f / 32.0f));
    float s, c;
    sincosf((float)l * inv, &s, &c);
    g_sc[i] = make_float2(s, c);
}

// ---------------------------------------------------------------------------
// Kernel 1: x = X @ W + b, fused RoPE, scatter packed bf16 to g_qh / g_kh.
// Block tile 128x128, K-step 16, 4-stage cp.async pipeline (f32 smem).
// 8 warps: 2(M) x 4(N), warp tile 64x32. bf16 m16n8k16 MMA (pack at frag load).
// ---------------------------------------------------------------------------
#define G1_ASTRIDE 20
#define G1_BSTRIDE 132
#define G1_ASTAGE  (128 * G1_ASTRIDE)
#define G1_BSTAGE  (16 * G1_BSTRIDE)
#define G1_SMEM    (4 * (G1_ASTAGE + G1_BSTAGE) * 4)

__global__ __launch_bounds__(256) void k_gemm1_rope(
    const float* __restrict__ X,
    const float* __restrict__ W,
    const float* __restrict__ bias)
{
    extern __shared__ float sh[];
    float* AsBase = sh;
    float* BsBase = sh + 4 * G1_ASTAGE;

    const int tid  = threadIdx.x;
    const int lane = tid & 31;
    const int warp = tid >> 5;
    const int wm   = warp >> 2;
    const int wn   = warp & 3;
    const int bm   = blockIdx.y;
    const int bn   = blockIdx.x;

    float acc[4][4][4];
    #pragma unroll
    for (int mi = 0; mi < 4; mi++)
        #pragma unroll
        for (int ni = 0; ni < 4; ni++)
            #pragma unroll
            for (int r = 0; r < 4; r++) acc[mi][ni][r] = 0.0f;

    const int ar  = tid >> 2;
    const int ac4 = tid & 3;
    const int br  = tid >> 5;
    const int bc4 = tid & 31;

    auto loadStage = [&](int kt, int s) {
        float* A = AsBase + s * G1_ASTAGE;
        float* B = BsBase + s * G1_BSTAGE;
        #pragma unroll
        for (int it = 0; it < 2; it++) {
            int r = ar + it * 64;
            cpasync16(&A[r * G1_ASTRIDE + ac4 * 4],
                      &X[(size_t)(bm * 128 + r) * HID + kt + ac4 * 4]);
        }
        #pragma unroll
        for (int it = 0; it < 2; it++) {
            int r = br + it * 8;
            cpasync16(&B[r * G1_BSTRIDE + bc4 * 4],
                      &W[(size_t)(kt + r) * OUTD + bn * 128 + bc4 * 4]);
        }
    };

    const int NK = HID / 16;   // 48
    #pragma unroll
    for (int s = 0; s < 3; s++) {
        loadStage(s * 16, s);
        asm volatile("cp.async.commit_group;");
    }

    const int kb  = (lane & 3) * 2;        // k base for fragments
    const int arow = wm * 64 + (lane >> 2);

    for (int i = 0; i < NK; i++) {
        asm volatile("cp.async.wait_group 2;");
        __syncthreads();
        if (i + 3 < NK) loadStage((i + 3) * 16, (i + 3) & 3);
        asm volatile("cp.async.commit_group;");

        const float* A = AsBase + (i & 3) * G1_ASTAGE;
        const float* B = BsBase + (i & 3) * G1_BSTAGE;

        unsigned bfr[4][2];
        #pragma unroll
        for (int ni = 0; ni < 4; ni++) {
            int col = wn * 32 + ni * 8 + (lane >> 2);
            bfr[ni][0] = packbf(B[kb * G1_BSTRIDE + col],       B[(kb + 1) * G1_BSTRIDE + col]);
            bfr[ni][1] = packbf(B[(kb + 8) * G1_BSTRIDE + col], B[(kb + 9) * G1_BSTRIDE + col]);
        }
        #pragma unroll
        for (int mi = 0; mi < 4; mi++) {
            int row = arow + mi * 16;
            unsigned afr[4];
            float2 p;
            p = *(const float2*)&A[row * G1_ASTRIDE + kb];           afr[0] = packbf(p.x, p.y);
            p = *(const float2*)&A[(row + 8) * G1_ASTRIDE + kb];     afr[1] = packbf(p.x, p.y);
            p = *(const float2*)&A[row * G1_ASTRIDE + kb + 8];       afr[2] = packbf(p.x, p.y);
            p = *(const float2*)&A[(row + 8) * G1_ASTRIDE + kb + 8]; afr[3] = packbf(p.x, p.y);
            #pragma unroll
            for (int ni = 0; ni < 4; ni++) mma16(acc[mi][ni], afr, bfr[ni]);
        }
    }

    // Epilogue: bias + RoPE (table) + scatter packed bf16.
    #pragma unroll
    for (int ni = 0; ni < 4; ni++) {
        int gc = bn * 128 + wn * 32 + ni * 8 + 2 * (lane & 3);  // even col
        int h  = gc >> 7;
        int s  = (gc >> 6) & 1;
        int d  = gc & 63;
        int pi = d >> 1;
        float b0 = bias[gc], b1 = bias[gc + 1];
        unsigned* dst = s ? g_kh : g_qh;
        #pragma unroll
        for (int mi = 0; mi < 4; mi++) {
            int gm0 = bm * 128 + wm * 64 + mi * 16 + (lane >> 2);
            #pragma unroll
            for (int half = 0; half < 2; half++) {
                int r  = gm0 + half * 8;
                int l  = r & (NL - 1);
                int bi = r >> 9;
                float2 sc = g_sc[l * 32 + pi];
                float x1 = acc[mi][ni][half * 2 + 0] + b0;
                float x2 = acc[mi][ni][half * 2 + 1] + b1;
                float o1 = x1 * sc.y - x2 * sc.x;
                float o2 = x1 * sc.x + x2 * sc.y;
                dst[(((size_t)bi * NHEADS + h) * NL + l) * (HS / 2) + pi] = packbf(o1, o2);
            }
        }
    }
}

// ---------------------------------------------------------------------------
// Kernel 2: logits[b,h,m,n] = (q[m,:] . k[n,:]) / 8, masked.
// Packed bf16 smem tiles (128 x 32 uints, stride 36), single sync.
// Fully-below-diagonal tiles fast-fill NEG. bf16 m16n8k16 MMA, zero-cvt loop.
// ---------------------------------------------------------------------------
#define A2_STRIDE 36
#define A2_TILE   (128 * A2_STRIDE)
#define A2_SMEM   (2 * A2_TILE * 4)

__global__ __launch_bounds__(256) void k_attn(
    const int* __restrict__ am, float* __restrict__ out)
{
    extern __shared__ unsigned sh2[];
    unsigned* Qs = sh2;
    unsigned* Ks = sh2 + A2_TILE;

    const int tid  = threadIdx.x;
    const int z    = blockIdx.z;          // b*12 + h
    const int m0   = blockIdx.y * 128;
    const int n0   = blockIdx.x * 128;

    const float NEG = -3.4028234663852886e38f;

    // Fast path: tile entirely strictly-below-diagonal -> all NEG.
    if (m0 >= n0 + 128) {
        const float4 negv = make_float4(NEG, NEG, NEG, NEG);
        #pragma unroll
        for (int it = 0; it < 16; it++) {
            int j = it * 256 + tid;
            int r = j >> 5;
            int c = j & 31;
            *(float4*)&out[((size_t)z * NL + m0 + r) * NL + n0 + c * 4] = negv;
        }
        return;
    }

    const int lane = tid & 31;
    const int warp = tid >> 5;
    const int wm   = warp >> 2;
    const int wn   = warp & 3;
    const int bi   = z / NHEADS;

    // Load 128x32-uint q and k tiles via cp.async (4 chunks of 16B per tile per thread).
    #pragma unroll
    for (int it = 0; it < 4; it++) {
        int j  = it * 256 + tid;      // 16B chunk id, 0..1023
        int r  = j >> 3;              // 8 chunks per row
        int c4 = j & 7;
        cpasync16(&Qs[r * A2_STRIDE + c4 * 4],
                  &g_qh[((size_t)z * NL + m0 + r) * (HS / 2) + c4 * 4]);
        cpasync16(&Ks[r * A2_STRIDE + c4 * 4],
                  &g_kh[((size_t)z * NL + n0 + r) * (HS / 2) + c4 * 4]);
    }
    asm volatile("cp.async.commit_group;");

    float acc[4][4][4];
    #pragma unroll
    for (int mi = 0; mi < 4; mi++)
        #pragma unroll
        for (int ni = 0; ni < 4; ni++)
            #pragma unroll
            for (int r = 0; r < 4; r++) acc[mi][ni][r] = 0.0f;

    asm volatile("cp.async.wait_group 0;");
    __syncthreads();

    const int arow = wm * 64 + (lane >> 2);
    #pragma unroll
    for (int kk8 = 0; kk8 < 4; kk8++) {           // each covers K=16 (8 packed)
        int kidx = kk8 * 8 + (lane & 3);
        unsigned bfr[4][2];
        #pragma unroll
        for (int ni = 0; ni < 4; ni++) {
            int nrow = wn * 32 + ni * 8 + (lane >> 2);
            bfr[ni][0] = Ks[nrow * A2_STRIDE + kidx];
            bfr[ni][1] = Ks[nrow * A2_STRIDE + kidx + 4];
        }
        #pragma unroll
        for (int mi = 0; mi < 4; mi++) {
            int row = arow + mi * 16;
            unsigned afr[4];
            afr[0] = Qs[row * A2_STRIDE + kidx];
            afr[1] = Qs[(row + 8) * A2_STRIDE + kidx];
            afr[2] = Qs[row * A2_STRIDE + kidx + 4];
            afr[3] = Qs[(row + 8) * A2_STRIDE + kidx + 4];
            #pragma unroll
            for (int ni = 0; ni < 4; ni++) mma16(acc[mi][ni], afr, bfr[ni]);
        }
    }

    // Masks: keep iff am[m] && am[n] && m <= n, else NEG.
    bool mok[4][2];
    #pragma unroll
    for (int mi = 0; mi < 4; mi++)
        #pragma unroll
        for (int half = 0; half < 2; half++)
            mok[mi][half] = am[bi * NL + m0 + wm * 64 + mi * 16 + (lane >> 2) + half * 8] != 0;
    bool nok[4][2];
    #pragma unroll
    for (int ni = 0; ni < 4; ni++) {
        int n = n0 + wn * 32 + ni * 8 + 2 * (lane & 3);
        nok[ni][0] = am[bi * NL + n] != 0;
        nok[ni][1] = am[bi * NL + n + 1] != 0;
    }

    #pragma unroll
    for (int mi = 0; mi < 4; mi++) {
        #pragma unroll
        for (int half = 0; half < 2; half++) {
            int gm = m0 + wm * 64 + mi * 16 + (lane >> 2) + half * 8;
            bool mo = mok[mi][half];
            #pragma unroll
            for (int ni = 0; ni < 4; ni++) {
                int gn = n0 + wn * 32 + ni * 8 + 2 * (lane & 3);
                float v0 = acc[mi][ni][half * 2 + 0] * 0.125f;
                float v1 = acc[mi][ni][half * 2 + 1] * 0.125f;
                float r0 = (mo && nok[ni][0] && gm <= gn)     ? v0 : NEG;
                float r1 = (mo && nok[ni][1] && gm <= gn + 1) ? v1 : NEG;
                *(float2*)&out[((size_t)z * NL + gm) * NL + gn] = make_float2(r0, r1);
            }
        }
    }
}

extern "C" void kernel_launch(void* const* d_in, const int* in_sizes, int n_in,
                              void* d_out, int out_size)
{
    const float* X    = (const float*)d_in[0];   // [8, 512, 768]
    const float* W    = (const float*)d_in[1];   // [768, 1536]
    const float* bias = (const float*)d_in[2];   // [1536]
    const int*   am   = (const int*)d_in[3];     // [8, 512]
    float* out        = (float*)d_out;           // [8, 12, 512, 512]

    (void)in_sizes; (void)n_in; (void)out_size;

    cudaFuncSetAttribute(k_gemm1_rope, cudaFuncAttributeMaxDynamicSharedMemorySize, G1_SMEM);
    cudaFuncSetAttribute(k_attn,       cudaFuncAttributeMaxDynamicSharedMemorySize, A2_SMEM);

    k_tab<<<64, 256>>>();
    k_gemm1_rope<<<dim3(OUTD / 128, (NB * NL) / 128), 256, G1_SMEM>>>(X, W, bias);
    k_attn<<<dim3(NL / 128, NL / 128, NB * NHEADS), 256, A2_SMEM>>>(am, out);
}

// round 5
// speedup vs baseline: 1.6777x; 1.1882x over previous
#include <cuda_runtime.h>
#include <cuda_bf16.h>
#include <cstdint>

#define NHEADS 12
#define HS     64
#define HID    768
#define OUTD   1536
#define NB     8
#define NL     512

// Rotated q/k scratch, packed bf16 pairs along d: [b, h, l, d/2].
__device__ unsigned g_qh[NB * NHEADS * NL * (HS / 2)];
__device__ unsigned g_kh[NB * NHEADS * NL * (HS / 2)];

__device__ __forceinline__ unsigned packbf(float lo, float hi) {
    __nv_bfloat162 v = __floats2bfloat162_rn(lo, hi);
    return *reinterpret_cast<unsigned*>(&v);
}

__device__ __forceinline__ void mma16(float c[4], const unsigned a[4], const unsigned b[2]) {
    asm volatile(
        "mma.sync.aligned.m16n8k16.row.col.f32.bf16.bf16.f32 "
        "{%0,%1,%2,%3}, {%4,%5,%6,%7}, {%8,%9}, {%0,%1,%2,%3};\n"
        : "+f"(c[0]), "+f"(c[1]), "+f"(c[2]), "+f"(c[3])
        : "r"(a[0]), "r"(a[1]), "r"(a[2]), "r"(a[3]), "r"(b[0]), "r"(b[1]));
}

__device__ __forceinline__ void ldmat4(unsigned a[4], const void* p) {
    unsigned sa = (unsigned)__cvta_generic_to_shared(p);
    asm volatile("ldmatrix.sync.aligned.m8n8.x4.shared.b16 {%0,%1,%2,%3}, [%4];"
                 : "=r"(a[0]), "=r"(a[1]), "=r"(a[2]), "=r"(a[3]) : "r"(sa));
}

__device__ __forceinline__ void cpasync16(void* s, const void* g) {
    unsigned sa = (unsigned)__cvta_generic_to_shared(s);
    asm volatile("cp.async.ca.shared.global [%0], [%1], 16;" :: "r"(sa), "l"(g));
}

// ---------------------------------------------------------------------------
// Kernel 1: x = X @ W + b, fused RoPE (__sinf/__cosf), scatter bf16 pairs.
// Block tile 128x128, K-step 16, register-staged smem double buffer.
// smem holds PACKED bf16: Ap[2][128][12]u (ldmatrix layout), Bp[2][8][136]u
// (k-pair-major). 8 warps 2(M)x4(N), warp 64x32, bf16 m16n8k16.
// ---------------------------------------------------------------------------
#define G1_ASTR  12
#define G1_BSTR  136
#define G1_ASZ   (128 * G1_ASTR)
#define G1_BSZ   (8 * G1_BSTR)
#define G1_SMEM  (2 * (G1_ASZ + G1_BSZ) * 4)

__global__ __launch_bounds__(256) void k_gemm1_rope(
    const float* __restrict__ X,
    const float* __restrict__ W,
    const float* __restrict__ bias)
{
    extern __shared__ unsigned sh[];
    unsigned* Ap = sh;                       // [2][128][12]
    unsigned* Bp = sh + 2 * G1_ASZ;          // [2][8][136]

    const int tid  = threadIdx.x;
    const int lane = tid & 31;
    const int warp = tid >> 5;
    const int wm   = warp >> 2;
    const int wn   = warp & 3;
    const int bm   = blockIdx.y;
    const int bn   = blockIdx.x;

    float acc[4][4][4];
    #pragma unroll
    for (int mi = 0; mi < 4; mi++)
        #pragma unroll
        for (int ni = 0; ni < 4; ni++)
            #pragma unroll
            for (int r = 0; r < 4; r++) acc[mi][ni][r] = 0.0f;

    // Global-load assignment.
    const int arow = tid >> 1;               // 0..127
    const int ah   = tid & 1;                // k half (8 floats)
    const int brow = tid >> 5;               // 0..7  (k-pair row)
    const int bc   = tid & 31;               // col group of 4
    const float* Xa = X + (size_t)(bm * 128 + arow) * HID + ah * 8;
    const float* Wb = W + (size_t)(2 * brow) * OUTD + bn * 128 + bc * 4;

    float4 a0, a1, b0, b1;
    auto ldg = [&](int kt) {
        a0 = *(const float4*)(Xa + kt);
        a1 = *(const float4*)(Xa + kt + 4);
        b0 = *(const float4*)(Wb + (size_t)kt * OUTD);
        b1 = *(const float4*)(Wb + (size_t)(kt + 1) * OUTD);
    };
    auto sts = [&](int s) {
        uint4 ua = make_uint4(packbf(a0.x, a0.y), packbf(a0.z, a0.w),
                              packbf(a1.x, a1.y), packbf(a1.z, a1.w));
        *(uint4*)&Ap[s * G1_ASZ + arow * G1_ASTR + ah * 4] = ua;
        uint4 ub = make_uint4(packbf(b0.x, b1.x), packbf(b0.y, b1.y),
                              packbf(b0.z, b1.z), packbf(b0.w, b1.w));
        *(uint4*)&Bp[s * G1_BSZ + brow * G1_BSTR + bc * 4] = ub;
    };

    ldg(0); sts(0); __syncthreads();

    const int NK = HID / 16;   // 48
    for (int i = 0; i < NK; i++) {
        if (i + 1 < NK) ldg((i + 1) * 16);

        const unsigned* A = Ap + (i & 1) * G1_ASZ;
        const unsigned* B = Bp + (i & 1) * G1_BSZ;

        unsigned bfr[4][2];
        #pragma unroll
        for (int ni = 0; ni < 4; ni++) {
            int col = wn * 32 + ni * 8 + (lane >> 2);
            bfr[ni][0] = B[(lane & 3) * G1_BSTR + col];
            bfr[ni][1] = B[((lane & 3) + 4) * G1_BSTR + col];
        }
        #pragma unroll
        for (int mi = 0; mi < 4; mi++) {
            unsigned afr[4];
            ldmat4(afr, &A[(wm * 64 + mi * 16 + (lane & 15)) * G1_ASTR + (lane >> 4) * 4]);
            #pragma unroll
            for (int ni = 0; ni < 4; ni++) mma16(acc[mi][ni], afr, bfr[ni]);
        }

        if (i + 1 < NK) sts((i + 1) & 1);
        __syncthreads();
    }

    // Epilogue: bias + RoPE + scatter packed bf16.
    #pragma unroll
    for (int ni = 0; ni < 4; ni++) {
        int gc = bn * 128 + wn * 32 + ni * 8 + 2 * (lane & 3);  // even col
        int h  = gc >> 7;
        int s  = (gc >> 6) & 1;
        int d  = gc & 63;
        int pi = d >> 1;
        float inv = exp2f(-(float)pi * (13.287712379549449f / 32.0f));
        float bb0 = bias[gc], bb1 = bias[gc + 1];
        unsigned* dst = s ? g_kh : g_qh;
        #pragma unroll
        for (int mi = 0; mi < 4; mi++) {
            int gm0 = bm * 128 + wm * 64 + mi * 16 + (lane >> 2);
            #pragma unroll
            for (int half = 0; half < 2; half++) {
                int r  = gm0 + half * 8;
                int l  = r & (NL - 1);
                int bi = r >> 9;
                float ang = (float)l * inv;
                float sn = __sinf(ang), cs = __cosf(ang);
                float x1 = acc[mi][ni][half * 2 + 0] + bb0;
                float x2 = acc[mi][ni][half * 2 + 1] + bb1;
                dst[(((size_t)bi * NHEADS + h) * NL + l) * (HS / 2) + pi] =
                    packbf(x1 * cs - x2 * sn, x1 * sn + x2 * cs);
            }
        }
    }
}

// ---------------------------------------------------------------------------
// Kernel 2: logits[b,h,m,n] = (q . k) / 8, masked. One block per (z, m-tile).
// Q tile loaded once (ldmatrix layout, stride 36); K tiles double-buffered
// cp.async so next tile's load hides under current tile's MMA + store.
// Below-diagonal tiles NEG-filled while the first loads are in flight.
// ---------------------------------------------------------------------------
#define A2_QSTR 36
#define A2_QSZ  (128 * A2_QSTR)
#define A2_KSTR 36
#define A2_KSZ  (128 * A2_KSTR)
#define A2_SMEM ((A2_QSZ + 2 * A2_KSZ) * 4)

__global__ __launch_bounds__(256) void k_attn(
    const int* __restrict__ am, float* __restrict__ out)
{
    extern __shared__ unsigned sh2[];
    unsigned* Qp = sh2;                       // [128][36]
    unsigned* Kp = sh2 + A2_QSZ;              // [2][128][36]

    const int tid  = threadIdx.x;
    const int lane = tid & 31;
    const int warp = tid >> 5;
    const int wm   = warp >> 2;
    const int wn   = warp & 3;
    const int mt   = blockIdx.x;              // m-tile 0..3
    const int z    = blockIdx.y;              // b*12 + h
    const int m0   = mt * 128;
    const int bi   = z / NHEADS;
    const float NEG = -3.4028234663852886e38f;

    // Issue Q load + first K tile load.
    const int lr  = tid >> 1;                 // row for Q/K chunk loads (2 chunks/row/thread)
    const int lc  = (tid & 1) * 16;           // starting uint (2 x 16B chunks)
    {
        const unsigned* qsrc = &g_qh[((size_t)z * NL + m0 + lr) * (HS / 2)];
        cpasync16(&Qp[lr * A2_QSTR + lc], qsrc + lc);
        cpasync16(&Qp[lr * A2_QSTR + lc + 4], qsrc + lc + 4);
        cpasync16(&Qp[lr * A2_QSTR + lc + 8], qsrc + lc + 8);
        cpasync16(&Qp[lr * A2_QSTR + lc + 12], qsrc + lc + 12);
        // wait: that's 4 chunks for 16 uints? lc in {0,16} invalid (row is 32 uints)
    }
    // (corrected below: each row has 32 uints = 8 chunks; 2 threads/row -> 4 chunks each)
    // NOTE: the loop above already issued exactly chunks lc..lc+15 (4x16B), covering
    // uints [lc, lc+16) — rows split as [0,16) and [16,32). OK.
    {
        const unsigned* ksrc = &g_kh[((size_t)z * NL + m0 + lr) * (HS / 2)];
        cpasync16(&Kp[lr * A2_KSTR + lc], ksrc + lc);
        cpasync16(&Kp[lr * A2_KSTR + lc + 4], ksrc + lc + 4);
        cpasync16(&Kp[lr * A2_KSTR + lc + 8], ksrc + lc + 8);
        cpasync16(&Kp[lr * A2_KSTR + lc + 12], ksrc + lc + 12);
    }
    asm volatile("cp.async.commit_group;");

    // NEG-fill below-diagonal tiles while loads are in flight.
    const float4 negv = make_float4(NEG, NEG, NEG, NEG);
    for (int nt = 0; nt < mt; nt++) {
        #pragma unroll
        for (int it = 0; it < 16; it++) {
            int j = it * 256 + tid;
            int r = j >> 5;
            int c = j & 31;
            *(float4*)&out[((size_t)z * NL + m0 + r) * NL + nt * 128 + c * 4] = negv;
        }
    }

    // m-side masks (fixed for the block).
    bool mok[4][2];
    #pragma unroll
    for (int mi = 0; mi < 4; mi++)
        #pragma unroll
        for (int half = 0; half < 2; half++)
            mok[mi][half] = am[bi * NL + m0 + wm * 64 + mi * 16 + (lane >> 2) + half * 8] != 0;

    asm volatile("cp.async.wait_group 0;");
    __syncthreads();

    for (int nt = mt; nt < 4; nt++) {
        const int buf = (nt - mt) & 1;
        // Prefetch next K tile.
        if (nt + 1 < 4) {
            const unsigned* ksrc = &g_kh[((size_t)z * NL + (nt + 1) * 128 + lr) * (HS / 2)];
            unsigned* kdst = &Kp[(buf ^ 1) * A2_KSZ + lr * A2_KSTR + lc];
            cpasync16(kdst,      ksrc + lc);
            cpasync16(kdst + 4,  ksrc + lc + 4);
            cpasync16(kdst + 8,  ksrc + lc + 8);
            cpasync16(kdst + 12, ksrc + lc + 12);
            asm volatile("cp.async.commit_group;");
        }

        const unsigned* K = Kp + buf * A2_KSZ;
        float acc[4][4][4];
        #pragma unroll
        for (int mi = 0; mi < 4; mi++)
            #pragma unroll
            for (int ni = 0; ni < 4; ni++)
                #pragma unroll
                for (int r = 0; r < 4; r++) acc[mi][ni][r] = 0.0f;

        #pragma unroll
        for (int kk8 = 0; kk8 < 4; kk8++) {
            int kidx = kk8 * 8 + (lane & 3);
            unsigned bfr[4][2];
            #pragma unroll
            for (int ni = 0; ni < 4; ni++) {
                int nrow = wn * 32 + ni * 8 + (lane >> 2);
                bfr[ni][0] = K[nrow * A2_KSTR + kidx];
                bfr[ni][1] = K[nrow * A2_KSTR + kidx + 4];
            }
            #pragma unroll
            for (int mi = 0; mi < 4; mi++) {
                unsigned afr[4];
                ldmat4(afr, &Qp[(wm * 64 + mi * 16 + (lane & 15)) * A2_QSTR
                                + kk8 * 8 + (lane >> 4) * 4]);
                #pragma unroll
                for (int ni = 0; ni < 4; ni++) mma16(acc[mi][ni], afr, bfr[ni]);
            }
        }

        // n-side masks + store.
        const int n0 = nt * 128;
        bool nok[4][2];
        #pragma unroll
        for (int ni = 0; ni < 4; ni++) {
            int n = n0 + wn * 32 + ni * 8 + 2 * (lane & 3);
            nok[ni][0] = am[bi * NL + n] != 0;
            nok[ni][1] = am[bi * NL + n + 1] != 0;
        }
        #pragma unroll
        for (int mi = 0; mi < 4; mi++) {
            #pragma unroll
            for (int half = 0; half < 2; half++) {
                int gm = m0 + wm * 64 + mi * 16 + (lane >> 2) + half * 8;
                bool mo = mok[mi][half];
                #pragma unroll
                for (int ni = 0; ni < 4; ni++) {
                    int gn = n0 + wn * 32 + ni * 8 + 2 * (lane & 3);
                    float v0 = acc[mi][ni][half * 2 + 0] * 0.125f;
                    float v1 = acc[mi][ni][half * 2 + 1] * 0.125f;
                    float r0 = (mo && nok[ni][0] && gm <= gn)     ? v0 : NEG;
                    float r1 = (mo && nok[ni][1] && gm <= gn + 1) ? v1 : NEG;
                    *(float2*)&out[((size_t)z * NL + gm) * NL + gn] = make_float2(r0, r1);
                }
            }
        }

        if (nt + 1 < 4) {
            asm volatile("cp.async.wait_group 0;");
            __syncthreads();
        }
    }
}

extern "C" void kernel_launch(void* const* d_in, const int* in_sizes, int n_in,
                              void* d_out, int out_size)
{
    const float* X    = (const float*)d_in[0];   // [8, 512, 768]
    const float* W    = (const float*)d_in[1];   // [768, 1536]
    const float* bias = (const float*)d_in[2];   // [1536]
    const int*   am   = (const int*)d_in[3];     // [8, 512]
    float* out        = (float*)d_out;           // [8, 12, 512, 512]

    (void)in_sizes; (void)n_in; (void)out_size;

    cudaFuncSetAttribute(k_gemm1_rope, cudaFuncAttributeMaxDynamicSharedMemorySize, G1_SMEM);
    cudaFuncSetAttribute(k_attn,       cudaFuncAttributeMaxDynamicSharedMemorySize, A2_SMEM);

    k_gemm1_rope<<<dim3(OUTD / 128, (NB * NL) / 128), 256, G1_SMEM>>>(X, W, bias);
    k_attn<<<dim3(4, NB * NHEADS), 256, A2_SMEM>>>(am, out);
}

// round 6
// speedup vs baseline: 2.2407x; 1.3355x over previous
#include <cuda_runtime.h>
#include <cuda_bf16.h>
#include <cstdint>

#define NHEADS 12
#define HS     64
#define HID    768
#define OUTD   1536
#define NB     8
#define NL     512

// Packed-bf16 copies of the GEMM1 operands (built once per launch by k_cvt).
// g_xh[row][kp]  = (X[row, 2kp],  X[row, 2kp+1])   : [4096][384] uints
// g_wh[kp][n]    = (W[2kp, n],    W[2kp+1, n])     : [384][1536] uints
__device__ unsigned g_xh[NB * NL * (HID / 2)];
__device__ unsigned g_wh[(HID / 2) * OUTD];

// Rotated q/k scratch, packed bf16 pairs along d: [b, h, l, d/2].
__device__ unsigned g_qh[NB * NHEADS * NL * (HS / 2)];
__device__ unsigned g_kh[NB * NHEADS * NL * (HS / 2)];

__device__ __forceinline__ unsigned packbf(float lo, float hi) {
    __nv_bfloat162 v = __floats2bfloat162_rn(lo, hi);
    return *reinterpret_cast<unsigned*>(&v);
}

__device__ __forceinline__ void mma16(float c[4], const unsigned a[4], const unsigned b[2]) {
    asm volatile(
        "mma.sync.aligned.m16n8k16.row.col.f32.bf16.bf16.f32 "
        "{%0,%1,%2,%3}, {%4,%5,%6,%7}, {%8,%9}, {%0,%1,%2,%3};\n"
        : "+f"(c[0]), "+f"(c[1]), "+f"(c[2]), "+f"(c[3])
        : "r"(a[0]), "r"(a[1]), "r"(a[2]), "r"(a[3]), "r"(b[0]), "r"(b[1]));
}

__device__ __forceinline__ void ldmat4(unsigned a[4], const void* p) {
    unsigned sa = (unsigned)__cvta_generic_to_shared(p);
    asm volatile("ldmatrix.sync.aligned.m8n8.x4.shared.b16 {%0,%1,%2,%3}, [%4];"
                 : "=r"(a[0]), "=r"(a[1]), "=r"(a[2]), "=r"(a[3]) : "r"(sa));
}

__device__ __forceinline__ void cpasync16(void* s, const void* g) {
    unsigned sa = (unsigned)__cvta_generic_to_shared(s);
    asm volatile("cp.async.ca.shared.global [%0], [%1], 16;" :: "r"(sa), "l"(g));
}

// ---------------------------------------------------------------------------
// Kernel 0: convert X, W to packed bf16 (uint4-vectorized).
// ---------------------------------------------------------------------------
#define NX4 ((NB * NL * (HID / 2)) / 4)       // 393216 uint4 for X
#define NW4 (((HID / 2) * OUTD) / 4)          // 147456 uint4 for W

__global__ __launch_bounds__(256) void k_cvt(
    const float* __restrict__ X, const float* __restrict__ W)
{
    int j = blockIdx.x * 256 + threadIdx.x;
    if (j < NX4) {
        const float4 a = ((const float4*)X)[2 * j];
        const float4 b = ((const float4*)X)[2 * j + 1];
        ((uint4*)g_xh)[j] = make_uint4(packbf(a.x, a.y), packbf(a.z, a.w),
                                       packbf(b.x, b.y), packbf(b.z, b.w));
    } else if (j < NX4 + NW4) {
        int i  = j - NX4;
        int kp = i / (OUTD / 4);
        int c4 = i % (OUTD / 4);
        const float4 a = ((const float4*)W)[(size_t)(2 * kp) * (OUTD / 4) + c4];
        const float4 b = ((const float4*)W)[(size_t)(2 * kp + 1) * (OUTD / 4) + c4];
        ((uint4*)g_wh)[i] = make_uint4(packbf(a.x, b.x), packbf(a.y, b.y),
                                       packbf(a.z, b.z), packbf(a.w, b.w));
    }
}

// ---------------------------------------------------------------------------
// Kernel 1: x = X @ W + b, fused RoPE, scatter bf16 pairs to g_qh / g_kh.
// Pure-bf16 4-stage cp.async pipeline, K-step 32, 24 iterations, no
// conversions and no load->store dependency in the main loop.
// 8 warps 2(M)x4(N), warp 64x32, bf16 m16n8k16.
// smem: As[4][128][20]u (ldmatrix-friendly), Bs[4][16][136]u (k-pair rows).
// ---------------------------------------------------------------------------
#define G1_ASTR  20
#define G1_BSTR  136
#define G1_ASZ   (128 * G1_ASTR)
#define G1_BSZ   (16 * G1_BSTR)
#define G1_SMEM  (4 * (G1_ASZ + G1_BSZ) * 4)

__global__ __launch_bounds__(256) void k_gemm1_rope(const float* __restrict__ bias)
{
    extern __shared__ unsigned sh[];
    unsigned* As = sh;                       // [4][128][20]
    unsigned* Bs = sh + 4 * G1_ASZ;          // [4][16][136]

    const int tid  = threadIdx.x;
    const int lane = tid & 31;
    const int warp = tid >> 5;
    const int wm   = warp >> 2;
    const int wn   = warp & 3;
    const int bm   = blockIdx.y;
    const int bn   = blockIdx.x;

    float acc[4][4][4];
    #pragma unroll
    for (int mi = 0; mi < 4; mi++)
        #pragma unroll
        for (int ni = 0; ni < 4; ni++)
            #pragma unroll
            for (int r = 0; r < 4; r++) acc[mi][ni][r] = 0.0f;

    // cp.async assignments: A 512 chunks/stage, B 512 chunks/stage; 2+2 per thread.
    const int aj0 = tid, aj1 = tid + 256;    // A chunk ids (row = j>>2, c4 = j&3)
    const int bj0 = tid, bj1 = tid + 256;    // B chunk ids (row = j>>5, c4 = j&31)

    auto loadStage = [&](int i, int s) {     // i = K-step index (16 pairs per step)
        unsigned* A = As + s * G1_ASZ;
        unsigned* B = Bs + s * G1_BSZ;
        const int ktp = i * 16;              // k-pair offset
        {
            int r = aj0 >> 2, c = aj0 & 3;
            cpasync16(&A[r * G1_ASTR + c * 4],
                      &g_xh[(size_t)(bm * 128 + r) * (HID / 2) + ktp + c * 4]);
            r = aj1 >> 2; c = aj1 & 3;
            cpasync16(&A[r * G1_ASTR + c * 4],
                      &g_xh[(size_t)(bm * 128 + r) * (HID / 2) + ktp + c * 4]);
        }
        {
            int r = bj0 >> 5, c = bj0 & 31;
            cpasync16(&B[r * G1_BSTR + c * 4],
                      &g_wh[(size_t)(ktp + r) * OUTD + bn * 128 + c * 4]);
            r = bj1 >> 5; c = bj1 & 31;
            cpasync16(&B[r * G1_BSTR + c * 4],
                      &g_wh[(size_t)(ktp + r) * OUTD + bn * 128 + c * 4]);
        }
    };

    const int NK = HID / 32;   // 24
    #pragma unroll
    for (int s = 0; s < 3; s++) {
        loadStage(s, s);
        asm volatile("cp.async.commit_group;");
    }

    for (int i = 0; i < NK; i++) {
        asm volatile("cp.async.wait_group 2;");
        __syncthreads();
        if (i + 3 < NK) loadStage(i + 3, (i + 3) & 3);
        asm volatile("cp.async.commit_group;");   // always commit: keeps count uniform

        const unsigned* A = As + (i & 3) * G1_ASZ;
        const unsigned* B = Bs + (i & 3) * G1_BSZ;

        #pragma unroll
        for (int kh = 0; kh < 2; kh++) {
            unsigned bfr[4][2];
            #pragma unroll
            for (int ni = 0; ni < 4; ni++) {
                int col = wn * 32 + ni * 8 + (lane >> 2);
                bfr[ni][0] = B[(kh * 8 + (lane & 3)) * G1_BSTR + col];
                bfr[ni][1] = B[(kh * 8 + (lane & 3) + 4) * G1_BSTR + col];
            }
            #pragma unroll
            for (int mi = 0; mi < 4; mi++) {
                unsigned afr[4];
                ldmat4(afr, &A[(wm * 64 + mi * 16 + (lane & 15)) * G1_ASTR
                               + kh * 8 + (lane >> 4) * 4]);
                #pragma unroll
                for (int ni = 0; ni < 4; ni++) mma16(acc[mi][ni], afr, bfr[ni]);
            }
        }
    }

    // Epilogue: bias + RoPE + scatter packed bf16.
    #pragma unroll
    for (int ni = 0; ni < 4; ni++) {
        int gc = bn * 128 + wn * 32 + ni * 8 + 2 * (lane & 3);  // even col
        int h  = gc >> 7;
        int s  = (gc >> 6) & 1;
        int d  = gc & 63;
        int pi = d >> 1;
        float inv = exp2f(-(float)pi * (13.287712379549449f / 32.0f));
        float bb0 = bias[gc], bb1 = bias[gc + 1];
        unsigned* dst = s ? g_kh : g_qh;
        #pragma unroll
        for (int mi = 0; mi < 4; mi++) {
            int gm0 = bm * 128 + wm * 64 + mi * 16 + (lane >> 2);
            #pragma unroll
            for (int half = 0; half < 2; half++) {
                int r  = gm0 + half * 8;
                int l  = r & (NL - 1);
                int bi = r >> 9;
                float ang = (float)l * inv;
                float sn = __sinf(ang), cs = __cosf(ang);
                float x1 = acc[mi][ni][half * 2 + 0] + bb0;
                float x2 = acc[mi][ni][half * 2 + 1] + bb1;
                dst[(((size_t)bi * NHEADS + h) * NL + l) * (HS / 2) + pi] =
                    packbf(x1 * cs - x2 * sn, x1 * sn + x2 * cs);
            }
        }
    }
}

// ---------------------------------------------------------------------------
// Kernel 2: logits[b,h,m,n] = (q . k) / 8, masked. One block per (z, m-tile).
// Q tile loaded once (ldmatrix layout, stride 36); K tiles double-buffered.
// Below-diagonal tiles NEG-filled while first loads are in flight.
// ---------------------------------------------------------------------------
#define A2_STR 36
#define A2_SZ  (128 * A2_STR)
#define A2_SMEM (3 * A2_SZ * 4)

__global__ __launch_bounds__(256) void k_attn(
    const int* __restrict__ am, float* __restrict__ out)
{
    extern __shared__ unsigned sh2[];
    unsigned* Qp = sh2;                       // [128][36]
    unsigned* Kp = sh2 + A2_SZ;               // [2][128][36]

    const int tid  = threadIdx.x;
    const int lane = tid & 31;
    const int warp = tid >> 5;
    const int wm   = warp >> 2;
    const int wn   = warp & 3;
    const int mt   = blockIdx.x;              // m-tile 0..3
    const int z    = blockIdx.y;              // b*12 + h
    const int m0   = mt * 128;
    const int bi   = z / NHEADS;
    const float NEG = -3.4028234663852886e38f;

    // Issue Q load + first K tile load (each row = 32 uints = 8 chunks;
    // 2 threads per row, 4 chunks each covering uints [lc, lc+16)).
    const int lr = tid >> 1;
    const int lc = (tid & 1) * 16;
    {
        const unsigned* qsrc = &g_qh[((size_t)z * NL + m0 + lr) * (HS / 2)];
        const unsigned* ksrc = &g_kh[((size_t)z * NL + m0 + lr) * (HS / 2)];
        #pragma unroll
        for (int c = 0; c < 4; c++) {
            cpasync16(&Qp[lr * A2_STR + lc + c * 4], qsrc + lc + c * 4);
            cpasync16(&Kp[lr * A2_STR + lc + c * 4], ksrc + lc + c * 4);
        }
    }
    asm volatile("cp.async.commit_group;");

    // NEG-fill below-diagonal tiles while loads are in flight.
    const float4 negv = make_float4(NEG, NEG, NEG, NEG);
    for (int nt = 0; nt < mt; nt++) {
        #pragma unroll
        for (int it = 0; it < 16; it++) {
            int j = it * 256 + tid;
            int r = j >> 5;
            int c = j & 31;
            *(float4*)&out[((size_t)z * NL + m0 + r) * NL + nt * 128 + c * 4] = negv;
        }
    }

    bool mok[4][2];
    #pragma unroll
    for (int mi = 0; mi < 4; mi++)
        #pragma unroll
        for (int half = 0; half < 2; half++)
            mok[mi][half] = am[bi * NL + m0 + wm * 64 + mi * 16 + (lane >> 2) + half * 8] != 0;

    asm volatile("cp.async.wait_group 0;");
    __syncthreads();

    for (int nt = mt; nt < 4; nt++) {
        const int buf = (nt - mt) & 1;
        if (nt + 1 < 4) {
            const unsigned* ksrc = &g_kh[((size_t)z * NL + (nt + 1) * 128 + lr) * (HS / 2)];
            unsigned* kdst = &Kp[(buf ^ 1) * A2_SZ + lr * A2_STR + lc];
            #pragma unroll
            for (int c = 0; c < 4; c++) cpasync16(kdst + c * 4, ksrc + lc + c * 4);
            asm volatile("cp.async.commit_group;");
        }

        const unsigned* K = Kp + buf * A2_SZ;
        float acc[4][4][4];
        #pragma unroll
        for (int mi = 0; mi < 4; mi++)
            #pragma unroll
            for (int ni = 0; ni < 4; ni++)
                #pragma unroll
                for (int r = 0; r < 4; r++) acc[mi][ni][r] = 0.0f;

        #pragma unroll
        for (int kk8 = 0; kk8 < 4; kk8++) {
            int kidx = kk8 * 8 + (lane & 3);
            unsigned bfr[4][2];
            #pragma unroll
            for (int ni = 0; ni < 4; ni++) {
                int nrow = wn * 32 + ni * 8 + (lane >> 2);
                bfr[ni][0] = K[nrow * A2_STR + kidx];
                bfr[ni][1] = K[nrow * A2_STR + kidx + 4];
            }
            #pragma unroll
            for (int mi = 0; mi < 4; mi++) {
                unsigned afr[4];
                ldmat4(afr, &Qp[(wm * 64 + mi * 16 + (lane & 15)) * A2_STR
                                + kk8 * 8 + (lane >> 4) * 4]);
                #pragma unroll
                for (int ni = 0; ni < 4; ni++) mma16(acc[mi][ni], afr, bfr[ni]);
            }
        }

        const int n0 = nt * 128;
        bool nok[4][2];
        #pragma unroll
        for (int ni = 0; ni < 4; ni++) {
            int n = n0 + wn * 32 + ni * 8 + 2 * (lane & 3);
            nok[ni][0] = am[bi * NL + n] != 0;
            nok[ni][1] = am[bi * NL + n + 1] != 0;
        }
        #pragma unroll
        for (int mi = 0; mi < 4; mi++) {
            #pragma unroll
            for (int half = 0; half < 2; half++) {
                int gm = m0 + wm * 64 + mi * 16 + (lane >> 2) + half * 8;
                bool mo = mok[mi][half];
                #pragma unroll
                for (int ni = 0; ni < 4; ni++) {
                    int gn = n0 + wn * 32 + ni * 8 + 2 * (lane & 3);
                    float v0 = acc[mi][ni][half * 2 + 0] * 0.125f;
                    float v1 = acc[mi][ni][half * 2 + 1] * 0.125f;
                    float r0 = (mo && nok[ni][0] && gm <= gn)     ? v0 : NEG;
                    float r1 = (mo && nok[ni][1] && gm <= gn + 1) ? v1 : NEG;
                    *(float2*)&out[((size_t)z * NL + gm) * NL + gn] = make_float2(r0, r1);
                }
            }
        }

        if (nt + 1 < 4) {
            asm volatile("cp.async.wait_group 0;");
            __syncthreads();
        }
    }
}

extern "C" void kernel_launch(void* const* d_in, const int* in_sizes, int n_in,
                              void* d_out, int out_size)
{
    const float* X    = (const float*)d_in[0];   // [8, 512, 768]
    const float* W    = (const float*)d_in[1];   // [768, 1536]
    const float* bias = (const float*)d_in[2];   // [1536]
    const int*   am   = (const int*)d_in[3];     // [8, 512]
    float* out        = (float*)d_out;           // [8, 12, 512, 512]

    (void)in_sizes; (void)n_in; (void)out_size;

    cudaFuncSetAttribute(k_gemm1_rope, cudaFuncAttributeMaxDynamicSharedMemorySize, G1_SMEM);
    cudaFuncSetAttribute(k_attn,       cudaFuncAttributeMaxDynamicSharedMemorySize, A2_SMEM);

    k_cvt<<<(NX4 + NW4 + 255) / 256, 256>>>(X, W);
    k_gemm1_rope<<<dim3(OUTD / 128, (NB * NL) / 128), 256, G1_SMEM>>>(bias);
    k_attn<<<dim3(4, NB * NHEADS), 256, A2_SMEM>>>(am, out);
}